// round 3
// baseline (speedup 1.0000x reference)
#include <cuda_runtime.h>
#include <math.h>

#define BB 32
#define SS 4096
#define DD 512          // INDIM == OUTDIM == 512
#define NCH 16
#define CS (SS / NCH)   // 256 keys per chunk

// ---- scratch (no allocations allowed) ----
__device__ float g_ht[BB * DD];          // 64 KB
__device__ float g_scores[BB * SS];      // 512 KB (raw masked scores)
__device__ float g_pm[BB * NCH];
__device__ float g_ps[BB * NCH];
__device__ float g_pc[BB * NCH * DD];    // 1 MB partial contexts
__device__ float g_cfin[BB * DD];

// memory_lengths may arrive as int32 or int64. Lengths are in [S/2, S] so the
// second 32-bit word is 0 iff the buffer is int64 (little-endian high word).
__device__ __forceinline__ int get_len(const int* __restrict__ L, int b) {
    return (L[1] == 0) ? L[2 * b] : L[b];
}

__device__ __forceinline__ float warp_allreduce_sum(float v) {
#pragma unroll
    for (int off = 16; off > 0; off >>= 1)
        v += __shfl_xor_sync(0xffffffffu, v, off);
    return v;
}

// ---------------------------------------------------------------------------
// Kernel 1: h_t[b][o] = dot(source[b,:], W_in[o,:])
// Warp owns output o and keeps W_in row in registers; src[b] staged in smem
// per batch -> W_in read from L2 exactly once (1 MB instead of 32 MB).
// ---------------------------------------------------------------------------
__global__ void __launch_bounds__(256) k_ht(const float* __restrict__ src,
                                            const float* __restrict__ Win) {
    __shared__ float4 sbuf[DD / 4];     // 2 KB: one source vector
    int wid = threadIdx.x >> 5, lane = threadIdx.x & 31;
    int o = blockIdx.x * 8 + wid;       // 64 blocks x 8 warps = 512 outputs

    const float4* w4 = (const float4*)(Win + (size_t)o * DD);
    float4 w[4];
#pragma unroll
    for (int j = 0; j < 4; j++) w[j] = w4[lane + 32 * j];

    for (int b = 0; b < BB; b++) {
        if (threadIdx.x < DD / 4)
            sbuf[threadIdx.x] = ((const float4*)(src + (size_t)b * DD))[threadIdx.x];
        __syncthreads();
        float dot = 0.f;
#pragma unroll
        for (int j = 0; j < 4; j++) {
            float4 x = sbuf[lane + 32 * j];
            dot += w[j].x * x.x + w[j].y * x.y + w[j].z * x.z + w[j].w * x.w;
        }
        dot = warp_allreduce_sum(dot);
        if (lane == 0) g_ht[b * DD + o] = dot;
        __syncthreads();
    }
}

// ---------------------------------------------------------------------------
// Kernel 2: single-pass online-softmax attention over one (batch, chunk).
// Reads memory_bank exactly once — the 256 MB HBM-bound kernel.
// Two keys per iteration: 8 LDG.128 issued back-to-back for MLP=8/warp.
// ---------------------------------------------------------------------------
__global__ void __launch_bounds__(256) k_attn(const float* __restrict__ mb,
                                              const int* __restrict__ L) {
    __shared__ float  cbuf[8][DD];   // 16 KB: per-warp scaled context
    __shared__ float2 ms[8];         // per-warp (m, sum)

    int b = blockIdx.y, chunk = blockIdx.x;
    int wid = threadIdx.x >> 5, lane = threadIdx.x & 31;
    int len = get_len(L, b);
    int s0 = chunk * CS;
    int send = min(s0 + CS, len);

    // h_t[b] held in registers: lane owns float4 groups {lane+32j}
    const float4* h4 = (const float4*)(g_ht + b * DD);
    float4 h[4];
#pragma unroll
    for (int j = 0; j < 4; j++) h[j] = h4[lane + 32 * j];

    float m = -INFINITY, ssum = 0.f;
    float4 c[4];
#pragma unroll
    for (int j = 0; j < 4; j++) c[j] = make_float4(0.f, 0.f, 0.f, 0.f);

    const float* bbase = mb + (size_t)b * SS * DD;
    int s = s0 + wid;

    // main loop: 2 keys per iteration, all 8 loads issued before any SHFL
    for (; s + 8 < send; s += 16) {
        const float4* k4a = (const float4*)(bbase + (size_t)s * DD);
        const float4* k4b = (const float4*)(bbase + (size_t)(s + 8) * DD);
        float4 ka[4], kb[4];
#pragma unroll
        for (int j = 0; j < 4; j++) ka[j] = k4a[lane + 32 * j];
#pragma unroll
        for (int j = 0; j < 4; j++) kb[j] = k4b[lane + 32 * j];

        float da = 0.f, db = 0.f;
#pragma unroll
        for (int j = 0; j < 4; j++) {
            da += h[j].x * ka[j].x + h[j].y * ka[j].y
                + h[j].z * ka[j].z + h[j].w * ka[j].w;
            db += h[j].x * kb[j].x + h[j].y * kb[j].y
                + h[j].z * kb[j].z + h[j].w * kb[j].w;
        }
        float sa = warp_allreduce_sum(da);
        float sb = warp_allreduce_sum(db);
        if (lane == 0) {
            g_scores[b * SS + s]     = sa;
            g_scores[b * SS + s + 8] = sb;
        }

        float mn = fmaxf(fmaxf(sa, sb), m);
        float sc = (m == -INFINITY) ? 0.f : __expf(m - mn);
        float pa = __expf(sa - mn);
        float pb = __expf(sb - mn);
        ssum = ssum * sc + pa + pb;
#pragma unroll
        for (int j = 0; j < 4; j++) {
            c[j].x = c[j].x * sc + pa * ka[j].x + pb * kb[j].x;
            c[j].y = c[j].y * sc + pa * ka[j].y + pb * kb[j].y;
            c[j].z = c[j].z * sc + pa * ka[j].z + pb * kb[j].z;
            c[j].w = c[j].w * sc + pa * ka[j].w + pb * kb[j].w;
        }
        m = mn;
    }
    // tail: at most one key per warp
    if (s < send) {
        const float4* k4 = (const float4*)(bbase + (size_t)s * DD);
        float4 kv[4];
        float dot = 0.f;
#pragma unroll
        for (int j = 0; j < 4; j++) {
            kv[j] = k4[lane + 32 * j];
            dot += h[j].x * kv[j].x + h[j].y * kv[j].y
                 + h[j].z * kv[j].z + h[j].w * kv[j].w;
        }
        float score = warp_allreduce_sum(dot);
        if (lane == 0) g_scores[b * SS + s] = score;

        float mn = fmaxf(score, m);
        float sc = (m == -INFINITY) ? 0.f : __expf(m - mn);
        float p = __expf(score - mn);
        ssum = ssum * sc + p;
#pragma unroll
        for (int j = 0; j < 4; j++) {
            c[j].x = c[j].x * sc + p * kv[j].x;
            c[j].y = c[j].y * sc + p * kv[j].y;
            c[j].z = c[j].z * sc + p * kv[j].z;
            c[j].w = c[j].w * sc + p * kv[j].w;
        }
        m = mn;
    }

    if (lane == 0) ms[wid] = make_float2(m, ssum);
    __syncthreads();

    float M = -INFINITY;
#pragma unroll
    for (int w = 0; w < 8; w++) M = fmaxf(M, ms[w].x);

    float f = (m == -INFINITY) ? 0.f : __expf(m - M);
    float4* cb4 = (float4*)cbuf[wid];
#pragma unroll
    for (int j = 0; j < 4; j++) {
        float4 v = c[j];
        v.x *= f; v.y *= f; v.z *= f; v.w *= f;
        cb4[lane + 32 * j] = v;
    }
    __syncthreads();

    int pi = b * NCH + chunk;
    if (threadIdx.x == 0) {
        float Sc = 0.f;
#pragma unroll
        for (int w = 0; w < 8; w++) {
            float fm = ms[w].x;
            float fw = (fm == -INFINITY) ? 0.f : __expf(fm - M);
            Sc += ms[w].y * fw;
        }
        g_pm[pi] = M;
        g_ps[pi] = Sc;
    }
    // deterministic fixed-order cross-warp sum
    for (int d = threadIdx.x; d < DD; d += 256) {
        float acc = 0.f;
#pragma unroll
        for (int w = 0; w < 8; w++) acc += cbuf[w][d];
        g_pc[pi * DD + d] = acc;
    }
}

// ---------------------------------------------------------------------------
// Kernel 3: merge chunk partials -> final context; write align_vectors.
// grid (BB, 8): each y-part handles 1/8 of dims and 1/8 of positions; the
// tiny chunk-merge scalars are recomputed redundantly per part.
// ---------------------------------------------------------------------------
__global__ void __launch_bounds__(256) k_reduce(const int* __restrict__ L,
                                                float* __restrict__ out) {
    int b = blockIdx.x, part = blockIdx.y;
    int len = get_len(L, b);

    float M = -INFINITY;
#pragma unroll
    for (int i = 0; i < NCH; i++) M = fmaxf(M, g_pm[b * NCH + i]);

    float e[NCH];
    float Ssum = 0.f;
#pragma unroll
    for (int i = 0; i < NCH; i++) {
        float mi = g_pm[b * NCH + i];
        e[i] = (mi == -INFINITY) ? 0.f : __expf(mi - M);
        Ssum += g_ps[b * NCH + i] * e[i];
    }
    float invS = 1.f / Ssum;

    // dims: 512/8 = 64 per part (threads 0..63 active)
    if (threadIdx.x < DD / 8) {
        int d = part * (DD / 8) + threadIdx.x;
        float acc = 0.f;
#pragma unroll
        for (int i = 0; i < NCH; i++) acc += g_pc[(b * NCH + i) * DD + d] * e[i];
        g_cfin[b * DD + d] = acc * invS;
    }

    // align positions: 4096/8 = 512 per part
    float* ali = out + BB * DD + (size_t)b * SS;
    int sbase = part * (SS / 8);
    for (int t = threadIdx.x; t < SS / 8; t += 256) {
        int s = sbase + t;
        ali[s] = (s < len) ? __expf(g_scores[b * SS + s] - M) * invS : 0.f;
    }
}

// ---------------------------------------------------------------------------
// Kernel 4: attn_h[b][o] = dot([c_final[b], source[b]], W_out[o,:])
// Warp keeps its 1024-wide W_out row in registers (8x float4/lane); x staged
// in smem per batch -> W_out read from L2 once (2 MB instead of 64 MB).
// ---------------------------------------------------------------------------
__global__ void __launch_bounds__(256) k_out(const float* __restrict__ src,
                                             const float* __restrict__ Wout,
                                             float* __restrict__ out) {
    __shared__ float4 xbuf[(2 * DD) / 4];   // 4 KB: [c_fin | src]
    int wid = threadIdx.x >> 5, lane = threadIdx.x & 31;
    int o = blockIdx.x * 8 + wid;           // 64 blocks x 8 warps = 512 outputs

    const float4* w4 = (const float4*)(Wout + (size_t)o * (2 * DD)); // 256 float4
    float4 w[8];
#pragma unroll
    for (int j = 0; j < 8; j++) w[j] = w4[lane + 32 * j];

    for (int b = 0; b < BB; b++) {
        int t = threadIdx.x;                // 256 threads, 256 float4
        xbuf[t] = (t < 128)
            ? ((const float4*)(g_cfin + b * DD))[t]
            : ((const float4*)(src + (size_t)b * DD))[t - 128];
        __syncthreads();
        float dot = 0.f;
#pragma unroll
        for (int j = 0; j < 8; j++) {
            float4 x = xbuf[lane + 32 * j];
            dot += w[j].x * x.x + w[j].y * x.y + w[j].z * x.z + w[j].w * x.w;
        }
        dot = warp_allreduce_sum(dot);
        if (lane == 0) out[b * DD + o] = dot;
        __syncthreads();
    }
}

// ---------------------------------------------------------------------------
extern "C" void kernel_launch(void* const* d_in, const int* in_sizes, int n_in,
                              void* d_out, int out_size) {
    const float* src  = (const float*)d_in[0];   // source        [32,1,512]
    const float* mb   = (const float*)d_in[1];   // memory_bank   [32,4096,512]
    const int*   L    = (const int*)  d_in[2];   // memory_lengths[32] (i32 or i64)
    const float* Win  = (const float*)d_in[3];   // W_in          [512,512]
    const float* Wout = (const float*)d_in[4];   // W_out         [512,1024]
    float* out = (float*)d_out;                  // [32*512 attn_h | 32*4096 align]

    k_ht    <<<DD / 8, 256>>>(src, Win);
    k_attn  <<<dim3(NCH, BB), 256>>>(mb, L);
    k_reduce<<<dim3(BB, 8), 256>>>(L, out);
    k_out   <<<DD / 8, 256>>>(src, Wout, out);
}